// round 8
// baseline (speedup 1.0000x reference)
#include <cuda_runtime.h>
#include <cuda_fp16.h>
#include <cstdint>

#define T_TOK 8192
#define DIN   4096
#define DOUT  4096
#define RRANK 64
#define NEXP  16
#define KCAT  5120
#define NCHUNK 80
#define SCALINGF 0.5f

// ---- scratch (static device globals: allocation-free) ----
__device__ __half g_Xhi[(size_t)T_TOK * KCAT];   // 80 MB
__device__ __half g_Xlo[(size_t)T_TOK * KCAT];   // 80 MB
__device__ __half g_W  [(size_t)DOUT * KCAT];    // 40 MB

// ---- helpers (compute_103-portable: cp.async + ldmatrix + mma.sync only) ----
__device__ __forceinline__ uint32_t smem_u32(const void* p) {
    return (uint32_t)__cvta_generic_to_shared(p);
}
__device__ __forceinline__ void cp_async16(uint32_t dst, const void* src) {
    asm volatile("cp.async.cg.shared.global [%0], [%1], 16;" :: "r"(dst), "l"(src) : "memory");
}
#define CP_COMMIT() asm volatile("cp.async.commit_group;" ::: "memory")
template<int N> __device__ __forceinline__ void cp_wait() {
    asm volatile("cp.async.wait_group %0;" :: "n"(N) : "memory");
}
__device__ __forceinline__ uint32_t sw128(uint32_t off) { return off ^ ((off >> 3) & 0x70); }

__device__ __forceinline__ void ldmx4(uint32_t* r, uint32_t addr) {
    asm volatile("ldmatrix.sync.aligned.m8n8.x4.shared.b16 {%0,%1,%2,%3}, [%4];"
                 : "=r"(r[0]), "=r"(r[1]), "=r"(r[2]), "=r"(r[3]) : "r"(addr));
}
__device__ __forceinline__ void mma16816(float* c, const uint32_t* a, const uint32_t* b) {
    asm volatile(
        "mma.sync.aligned.m16n8k16.row.col.f32.f16.f16.f32 "
        "{%0,%1,%2,%3}, {%4,%5,%6,%7}, {%8,%9}, {%0,%1,%2,%3};"
        : "+f"(c[0]), "+f"(c[1]), "+f"(c[2]), "+f"(c[3])
        : "r"(a[0]), "r"(a[1]), "r"(a[2]), "r"(a[3]), "r"(b[0]), "r"(b[1]));
}

// ---------------------------------------------------------------------------
// Prep 1: Wcat = [base_w | 0.5*B] -> fp16
// ---------------------------------------------------------------------------
__global__ void __launch_bounds__(256) wprep_kernel(const float* __restrict__ bw,
                                                    const float* __restrict__ Bm) {
    int k = blockIdx.x * 256 + threadIdx.x;
    int o = blockIdx.y;
    float v;
    if (k < DIN) v = bw[(size_t)o * DIN + k];
    else {
        int km = k - DIN;
        v = SCALINGF * Bm[((size_t)(km >> 6) * DOUT + o) * RRANK + (km & 63)];
    }
    g_W[(size_t)o * KCAT + k] = __float2half_rn(v);
}

// ---------------------------------------------------------------------------
// Prep 2: x -> fp16 hi/lo into Xcat cols [0, DIN)
// ---------------------------------------------------------------------------
__global__ void __launch_bounds__(256) xconv_kernel(const float* __restrict__ x) {
    int k = blockIdx.x * 256 + threadIdx.x;
    int t = blockIdx.y;
    float v = x[(size_t)t * DIN + k];
    __half hi = __float2half_rn(v);
    size_t idx = (size_t)t * KCAT + k;
    g_Xhi[idx] = hi;
    g_Xlo[idx] = __float2half_rn(v - __half2float(hi));
}

// ---------------------------------------------------------------------------
// Prep 3: per-token h = x@A^T, logits = x@router^T, softmax/top2,
//         Xcat cols [DIN, KCAT) = combine[e]*h[r] (fp16 hi/lo)
// ---------------------------------------------------------------------------
__global__ void __launch_bounds__(128) hlroute_kernel(const float* __restrict__ x,
                                                      const float* __restrict__ A,
                                                      const float* __restrict__ Rw) {
    __shared__ float sx[DIN];
    __shared__ float sh[80];
    __shared__ float scomb[NEXP];
    int t = blockIdx.x, tid = threadIdx.x;
    float4* sx4 = (float4*)sx;
    const float4* xr = (const float4*)(x + (size_t)t * DIN);
    for (int i = tid; i < DIN / 4; i += 128) sx4[i] = xr[i];
    __syncthreads();
    if (tid < 80) {
        const float4* w = (const float4*)(tid < 64 ? A + (size_t)tid * DIN
                                                   : Rw + (size_t)(tid - 64) * DIN);
        float a0 = 0.f, a1 = 0.f, a2 = 0.f, a3 = 0.f;
        #pragma unroll 4
        for (int i = 0; i < DIN / 4; i += 4) {
            float4 p, q;
            p = sx4[i + 0]; q = __ldg(w + i + 0); a0 += p.x*q.x + p.y*q.y + p.z*q.z + p.w*q.w;
            p = sx4[i + 1]; q = __ldg(w + i + 1); a1 += p.x*q.x + p.y*q.y + p.z*q.z + p.w*q.w;
            p = sx4[i + 2]; q = __ldg(w + i + 2); a2 += p.x*q.x + p.y*q.y + p.z*q.z + p.w*q.w;
            p = sx4[i + 3]; q = __ldg(w + i + 3); a3 += p.x*q.x + p.y*q.y + p.z*q.z + p.w*q.w;
        }
        sh[tid] = (a0 + a1) + (a2 + a3);
    }
    __syncthreads();
    if (tid == 0) {
        float mx = -1e30f;
        for (int e = 0; e < NEXP; e++) mx = fmaxf(mx, sh[64 + e]);
        float p[NEXP], se = 0.f;
        for (int e = 0; e < NEXP; e++) { p[e] = expf(sh[64 + e] - mx); se += p[e]; }
        for (int e = 0; e < NEXP; e++) p[e] /= se;
        int i1 = 0;
        for (int e = 1; e < NEXP; e++) if (p[e] > p[i1]) i1 = e;
        int i2 = (i1 == 0) ? 1 : 0;
        for (int e = 0; e < NEXP; e++) if (e != i1 && p[e] > p[i2]) i2 = e;
        float swt = p[i1] + p[i2] + 1e-6f;
        for (int e = 0; e < NEXP; e++) scomb[e] = 0.f;
        scomb[i1] = p[i1] / swt;
        scomb[i2] = p[i2] / swt;
    }
    __syncthreads();
    size_t base = (size_t)t * KCAT + DIN;
    for (int i = tid; i < NEXP * RRANK; i += 128) {
        float v = scomb[i >> 6] * sh[i & 63];
        __half hi = __float2half_rn(v);
        g_Xhi[base + i] = hi;
        g_Xlo[base + i] = __float2half_rn(v - __half2float(hi));
    }
}

// ---------------------------------------------------------------------------
// Main GEMM: out[T,DOUT] = (Xhi+Xlo) @ W^T + bias     (fp16 mma.sync, f32 acc)
// CTA tile 128x128, K-chunk 64, 3-stage cp.async, 8 warps (warp tile 32x64).
// ---------------------------------------------------------------------------
#define BM 128
#define BN 128
#define BK 64
#define STAGES 3
#define STAGE_BYTES 49152u   // Xhi 16K | Xlo 16K | W 16K
#define GEMM_SMEM (STAGES * STAGE_BYTES + 1024)

__global__ void __launch_bounds__(256, 1) gemm_kernel(const float* __restrict__ bias,
                                                      float* __restrict__ out) {
    extern __shared__ char dyn[];
    uint32_t sbase = (smem_u32(dyn) + 1023u) & ~1023u;

    const int tid  = threadIdx.x;
    const int wid  = tid >> 5, lane = tid & 31;
    const int m0 = blockIdx.y * BM, n0 = blockIdx.x * BN;
    const int wm = (wid & 3) * 32, wn = (wid >> 2) * 64;

    auto load_chunk = [&](int c, int s) {
        uint32_t st = sbase + (uint32_t)s * STAGE_BYTES;
        size_t gk = (size_t)c * BK;
        #pragma unroll
        for (int u = 0; u < 4; u++) {
            int v = u * 256 + tid;              // 0..1023 : 128 rows x 8 chunks
            int row = v >> 3, c16 = v & 7;
            uint32_t so = sw128((uint32_t)(row * 128 + c16 * 16));
            size_t gx = (size_t)(m0 + row) * KCAT + gk + c16 * 8;
            cp_async16(st + so,          g_Xhi + gx);
            cp_async16(st + 16384u + so, g_Xlo + gx);
            size_t gw = (size_t)(n0 + row) * KCAT + gk + c16 * 8;
            cp_async16(st + 32768u + so, g_W + gw);
        }
    };

    float acc[2][8][4];
    #pragma unroll
    for (int i = 0; i < 2; i++)
        #pragma unroll
        for (int j = 0; j < 8; j++)
            #pragma unroll
            for (int q = 0; q < 4; q++) acc[i][j][q] = 0.f;

    load_chunk(0, 0); CP_COMMIT();
    load_chunk(1, 1); CP_COMMIT();

    for (int c = 0; c < NCHUNK; c++) {
        cp_wait<STAGES - 2>();
        __syncthreads();
        // prefetch chunk c+2 into slot (c+2)%3 == (c-1)%3 (freed by the sync above)
        if (c + STAGES - 1 < NCHUNK) { load_chunk(c + STAGES - 1, (c + STAGES - 1) % STAGES); CP_COMMIT(); }

        uint32_t st  = sbase + (uint32_t)(c % STAGES) * STAGE_BYTES;
        uint32_t stl = st + 16384u, stw = st + 32768u;
        #pragma unroll
        for (int kk = 0; kk < BK; kk += 16) {
            uint32_t ah[8], al[8], bb[16];
            #pragma unroll
            for (int mt = 0; mt < 2; mt++) {
                int row = wm + mt * 16 + (lane & 7) + ((lane >> 3) & 1) * 8;
                int kb  = kk + (lane >> 4) * 8;
                uint32_t so = sw128((uint32_t)(row * 128 + kb * 2));
                ldmx4(ah + mt * 4, st + so);
                ldmx4(al + mt * 4, stl + so);
            }
            #pragma unroll
            for (int nt = 0; nt < 4; nt++) {
                int nrow = wn + nt * 16 + (lane & 7) + (lane >> 4) * 8;
                int kb   = kk + ((lane >> 3) & 1) * 8;
                uint32_t so = sw128((uint32_t)(nrow * 128 + kb * 2));
                ldmx4(bb + nt * 4, stw + so);
            }
            #pragma unroll
            for (int mt = 0; mt < 2; mt++)
                #pragma unroll
                for (int nj = 0; nj < 8; nj++) {
                    mma16816(acc[mt][nj], ah + mt * 4, bb + nj * 2);
                    mma16816(acc[mt][nj], al + mt * 4, bb + nj * 2);
                }
        }
    }

    // epilogue: register accumulators -> gmem with bias
    #pragma unroll
    for (int mt = 0; mt < 2; mt++) {
        int r0 = m0 + wm + mt * 16 + (lane >> 2);
        #pragma unroll
        for (int nj = 0; nj < 8; nj++) {
            int col = n0 + wn + nj * 8 + (lane & 3) * 2;
            float b0 = __ldg(bias + col), b1 = __ldg(bias + col + 1);
            float* p = out + (size_t)r0 * DOUT + col;
            p[0] = acc[mt][nj][0] + b0;
            p[1] = acc[mt][nj][1] + b1;
            float* q = p + (size_t)8 * DOUT;
            q[0] = acc[mt][nj][2] + b0;
            q[1] = acc[mt][nj][3] + b1;
        }
    }
}

// ---------------------------------------------------------------------------
// kernel_launch
// ---------------------------------------------------------------------------
extern "C" void kernel_launch(void* const* d_in, const int* in_sizes, int n_in,
                              void* d_out, int out_size) {
    const float* x      = (const float*)d_in[0];
    const float* base_w = (const float*)d_in[1];
    const float* base_b = (const float*)d_in[2];
    const float* A      = (const float*)d_in[3];
    const float* Bm     = (const float*)d_in[4];
    const float* router = (const float*)d_in[5];
    float* out = (float*)d_out;

    cudaFuncSetAttribute(gemm_kernel, cudaFuncAttributeMaxDynamicSharedMemorySize, GEMM_SMEM);

    wprep_kernel<<<dim3(KCAT / 256, DOUT), 256>>>(base_w, Bm);
    xconv_kernel<<<dim3(DIN / 256, T_TOK), 256>>>(x);
    hlroute_kernel<<<T_TOK, 128>>>(x, A, router);
    gemm_kernel<<<dim3(DOUT / BN, T_TOK / BM), 256, GEMM_SMEM>>>(base_b, out);
}

// round 12
// speedup vs baseline: 6.1615x; 6.1615x over previous
#include <cuda_runtime.h>
#include <cuda_fp16.h>
#include <cstdint>

#define T_TOK 8192
#define DIN   4096
#define DOUT  4096
#define RRANK 64
#define NEXP  16
#define KCAT  5120
#define NCHUNK 80
#define SCALINGF 0.5f

// ---- scratch (static device globals: allocation-free) ----
__device__ __half g_Xhi[(size_t)T_TOK * KCAT];   // 80 MB  (cols 0:4096 = x_hi, 4096:5120 = moe ext)
__device__ __half g_Xlo[(size_t)T_TOK * DIN];    // 64 MB  (x_lo, routing GEMM only)
__device__ __half g_W  [(size_t)DOUT * KCAT];    // 40 MB  ([base_w | 0.5*B])
__device__ __half g_W2 [(size_t)128 * DIN];      // 1 MB   ([A; router; 0] padded to 128 rows)
__device__ float  g_HL [(size_t)T_TOK * 128];    // 4 MB   (h | logits | pad)

// ---- helpers (compute_103-portable: cp.async + ldmatrix + mma.sync) ----
__device__ __forceinline__ uint32_t smem_u32(const void* p) {
    return (uint32_t)__cvta_generic_to_shared(p);
}
__device__ __forceinline__ void cp_async16(uint32_t dst, const void* src) {
    asm volatile("cp.async.cg.shared.global [%0], [%1], 16;" :: "r"(dst), "l"(src) : "memory");
}
#define CP_COMMIT() asm volatile("cp.async.commit_group;" ::: "memory")
template<int N> __device__ __forceinline__ void cp_wait() {
    asm volatile("cp.async.wait_group %0;" :: "n"(N) : "memory");
}
__device__ __forceinline__ uint32_t sw128(uint32_t off) { return off ^ ((off >> 3) & 0x70); }

__device__ __forceinline__ void ldmx4(uint32_t* r, uint32_t addr) {
    asm volatile("ldmatrix.sync.aligned.m8n8.x4.shared.b16 {%0,%1,%2,%3}, [%4];"
                 : "=r"(r[0]), "=r"(r[1]), "=r"(r[2]), "=r"(r[3]) : "r"(addr));
}
__device__ __forceinline__ void mma16816(float* c, const uint32_t* a, const uint32_t* b) {
    asm volatile(
        "mma.sync.aligned.m16n8k16.row.col.f32.f16.f16.f32 "
        "{%0,%1,%2,%3}, {%4,%5,%6,%7}, {%8,%9}, {%0,%1,%2,%3};"
        : "+f"(c[0]), "+f"(c[1]), "+f"(c[2]), "+f"(c[3])
        : "r"(a[0]), "r"(a[1]), "r"(a[2]), "r"(a[3]), "r"(b[0]), "r"(b[1]));
}

// ---------------------------------------------------------------------------
// Prep 1: Wcat = [base_w | 0.5*B] -> fp16
// ---------------------------------------------------------------------------
__global__ void __launch_bounds__(256) wprep_kernel(const float* __restrict__ bw,
                                                    const float* __restrict__ Bm) {
    int k = blockIdx.x * 256 + threadIdx.x;
    int o = blockIdx.y;
    float v;
    if (k < DIN) v = bw[(size_t)o * DIN + k];
    else {
        int km = k - DIN;
        v = SCALINGF * Bm[((size_t)(km >> 6) * DOUT + o) * RRANK + (km & 63)];
    }
    g_W[(size_t)o * KCAT + k] = __float2half_rn(v);
}

// ---------------------------------------------------------------------------
// Prep 1b: W2 = [A ; router ; 0] -> fp16, 128 x 4096
// ---------------------------------------------------------------------------
__global__ void __launch_bounds__(256) w2prep_kernel(const float* __restrict__ A,
                                                     const float* __restrict__ Rw) {
    int k = blockIdx.x * 256 + threadIdx.x;
    int r = blockIdx.y;
    float v = 0.f;
    if (r < RRANK)          v = A [(size_t)r * DIN + k];
    else if (r < RRANK + NEXP) v = Rw[(size_t)(r - RRANK) * DIN + k];
    g_W2[(size_t)r * DIN + k] = __float2half_rn(v);
}

// ---------------------------------------------------------------------------
// Prep 2: x -> fp16 hi (stride KCAT) + lo (stride DIN)
// ---------------------------------------------------------------------------
__global__ void __launch_bounds__(256) xconv_kernel(const float* __restrict__ x) {
    int k = blockIdx.x * 256 + threadIdx.x;
    int t = blockIdx.y;
    float v = x[(size_t)t * DIN + k];
    __half hi = __float2half_rn(v);
    g_Xhi[(size_t)t * KCAT + k] = hi;
    g_Xlo[(size_t)t * DIN + k]  = __float2half_rn(v - __half2float(hi));
}

// ---------------------------------------------------------------------------
// Routing GEMM: HL[T,128] = (Xhi+Xlo)[:, :4096] @ W2^T   (2-pass hi/lo fp16)
// Tile 64x128, 8 warps (warp tile 16x64), K-chunk 64, 3-stage cp.async.
// ---------------------------------------------------------------------------
#define HL_ST_BYTES 32768u   // Ahi 8K | Alo 8K | W2 16K
#define HL_SMEM (3 * HL_ST_BYTES + 1024)
#define HL_NCH  (DIN / 64)

__global__ void __launch_bounds__(256, 1) hl_gemm_kernel() {
    extern __shared__ char dyn[];
    uint32_t sbase = (smem_u32(dyn) + 1023u) & ~1023u;
    const int tid = threadIdx.x, wid = tid >> 5, lane = tid & 31;
    const int m0 = blockIdx.y * 64;
    const int wm = (wid & 3) * 16, wn = (wid >> 2) * 64;

    auto load_chunk = [&](int c, int s) {
        uint32_t st = sbase + (uint32_t)s * HL_ST_BYTES;
        size_t gk = (size_t)c * 64;
        #pragma unroll
        for (int u = 0; u < 2; u++) {                    // A: 64 rows x 8 c16
            int v = u * 256 + tid; int row = v >> 3, c16 = v & 7;
            uint32_t so = sw128((uint32_t)(row * 128 + c16 * 16));
            cp_async16(st + so,         g_Xhi + (size_t)(m0 + row) * KCAT + gk + c16 * 8);
            cp_async16(st + 8192u + so, g_Xlo + (size_t)(m0 + row) * DIN  + gk + c16 * 8);
        }
        #pragma unroll
        for (int u = 0; u < 4; u++) {                    // W2: 128 rows x 8 c16
            int v = u * 256 + tid; int row = v >> 3, c16 = v & 7;
            uint32_t so = sw128((uint32_t)(row * 128 + c16 * 16));
            cp_async16(st + 16384u + so, g_W2 + (size_t)row * DIN + gk + c16 * 8);
        }
    };

    float acc[8][4];
    #pragma unroll
    for (int j = 0; j < 8; j++)
        #pragma unroll
        for (int q = 0; q < 4; q++) acc[j][q] = 0.f;

    load_chunk(0, 0); CP_COMMIT();
    load_chunk(1, 1); CP_COMMIT();

    for (int c = 0; c < HL_NCH; c++) {
        cp_wait<1>();
        __syncthreads();
        if (c + 2 < HL_NCH) { load_chunk(c + 2, (c + 2) % 3); CP_COMMIT(); }

        uint32_t st = sbase + (uint32_t)(c % 3) * HL_ST_BYTES;
        #pragma unroll
        for (int kk = 0; kk < 64; kk += 16) {
            uint32_t ah[4], al[4], bb[16];
            {
                int row = wm + (lane & 7) + ((lane >> 3) & 1) * 8;
                int kb  = kk + (lane >> 4) * 8;
                uint32_t so = sw128((uint32_t)(row * 128 + kb * 2));
                ldmx4(ah, st + so);
                ldmx4(al, st + 8192u + so);
            }
            #pragma unroll
            for (int nt = 0; nt < 4; nt++) {
                int nrow = wn + nt * 16 + (lane & 7) + (lane >> 4) * 8;
                int kb   = kk + ((lane >> 3) & 1) * 8;
                ldmx4(bb + nt * 4, st + 16384u + sw128((uint32_t)(nrow * 128 + kb * 2)));
            }
            #pragma unroll
            for (int nj = 0; nj < 8; nj++) {
                mma16816(acc[nj], ah, bb + nj * 2);
                mma16816(acc[nj], al, bb + nj * 2);
            }
        }
    }

    int r0 = m0 + wm + (lane >> 2);
    #pragma unroll
    for (int nj = 0; nj < 8; nj++) {
        int col = wn + nj * 8 + (lane & 3) * 2;
        float* p = g_HL + (size_t)r0 * 128 + col;
        p[0] = acc[nj][0]; p[1] = acc[nj][1];
        p[128 * 8] = acc[nj][2]; p[128 * 8 + 1] = acc[nj][3];
    }
}

// ---------------------------------------------------------------------------
// Routing post: softmax/top2 over logits, Xhi ext cols = combine[e]*h[r]
// ---------------------------------------------------------------------------
__global__ void __launch_bounds__(128) hlpost_kernel() {
    __shared__ float sh[RRANK];
    __shared__ float scomb[NEXP];
    int t = blockIdx.x, tid = threadIdx.x;
    if (tid < RRANK) sh[tid] = g_HL[(size_t)t * 128 + tid];
    if (tid == 0) {
        const float* lg = g_HL + (size_t)t * 128 + RRANK;
        float mx = -1e30f;
        for (int e = 0; e < NEXP; e++) mx = fmaxf(mx, lg[e]);
        float p[NEXP], se = 0.f;
        for (int e = 0; e < NEXP; e++) { p[e] = expf(lg[e] - mx); se += p[e]; }
        for (int e = 0; e < NEXP; e++) p[e] /= se;
        int i1 = 0;
        for (int e = 1; e < NEXP; e++) if (p[e] > p[i1]) i1 = e;
        int i2 = (i1 == 0) ? 1 : 0;
        for (int e = 0; e < NEXP; e++) if (e != i1 && p[e] > p[i2]) i2 = e;
        float swt = p[i1] + p[i2] + 1e-6f;
        for (int e = 0; e < NEXP; e++) scomb[e] = 0.f;
        scomb[i1] = p[i1] / swt;
        scomb[i2] = p[i2] / swt;
    }
    __syncthreads();
    size_t base = (size_t)t * KCAT + DIN;
    #pragma unroll
    for (int i = tid; i < NEXP * RRANK; i += 128)
        g_Xhi[base + i] = __float2half_rn(scomb[i >> 6] * sh[i & 63]);
}

// ---------------------------------------------------------------------------
// Main GEMM: out[T,DOUT] = Xhi @ W^T + bias    (single-pass fp16, f32 acc)
// CTA tile 128x256, 8 warps (warp tile 64x64), K-chunk 64, 3-stage cp.async.
// ---------------------------------------------------------------------------
#define BM 128
#define BN 256
#define BK 64
#define STAGE_BYTES 49152u   // A 16K | B 32K
#define GEMM_SMEM (3 * STAGE_BYTES + 1024)

__global__ void __launch_bounds__(256, 1) gemm_kernel(const float* __restrict__ bias,
                                                      float* __restrict__ out) {
    extern __shared__ char dyn[];
    uint32_t sbase = (smem_u32(dyn) + 1023u) & ~1023u;
    const int tid = threadIdx.x, wid = tid >> 5, lane = tid & 31;
    const int m0 = blockIdx.y * BM, n0 = blockIdx.x * BN;
    const int wm = (wid & 1) * 64, wn = (wid >> 1) * 64;

    auto load_chunk = [&](int c, int s) {
        uint32_t st = sbase + (uint32_t)s * STAGE_BYTES;
        size_t gk = (size_t)c * BK;
        #pragma unroll
        for (int u = 0; u < 4; u++) {                    // A: 128 rows x 8 c16
            int v = u * 256 + tid; int row = v >> 3, c16 = v & 7;
            uint32_t so = sw128((uint32_t)(row * 128 + c16 * 16));
            cp_async16(st + so, g_Xhi + (size_t)(m0 + row) * KCAT + gk + c16 * 8);
        }
        #pragma unroll
        for (int u = 0; u < 8; u++) {                    // B: 256 rows x 8 c16
            int v = u * 256 + tid; int row = v >> 3, c16 = v & 7;
            uint32_t so = sw128((uint32_t)(row * 128 + c16 * 16));
            cp_async16(st + 16384u + so, g_W + (size_t)(n0 + row) * KCAT + gk + c16 * 8);
        }
    };

    float acc[4][8][4];
    #pragma unroll
    for (int i = 0; i < 4; i++)
        #pragma unroll
        for (int j = 0; j < 8; j++)
            #pragma unroll
            for (int q = 0; q < 4; q++) acc[i][j][q] = 0.f;

    load_chunk(0, 0); CP_COMMIT();
    load_chunk(1, 1); CP_COMMIT();

    for (int c = 0; c < NCHUNK; c++) {
        cp_wait<1>();
        __syncthreads();
        if (c + 2 < NCHUNK) { load_chunk(c + 2, (c + 2) % 3); CP_COMMIT(); }

        uint32_t st = sbase + (uint32_t)(c % 3) * STAGE_BYTES;
        #pragma unroll
        for (int kk = 0; kk < BK; kk += 16) {
            uint32_t ah[16], bb[16];
            #pragma unroll
            for (int mt = 0; mt < 4; mt++) {
                int row = wm + mt * 16 + (lane & 7) + ((lane >> 3) & 1) * 8;
                int kb  = kk + (lane >> 4) * 8;
                ldmx4(ah + mt * 4, st + sw128((uint32_t)(row * 128 + kb * 2)));
            }
            #pragma unroll
            for (int nt = 0; nt < 4; nt++) {
                int nrow = wn + nt * 16 + (lane & 7) + (lane >> 4) * 8;
                int kb   = kk + ((lane >> 3) & 1) * 8;
                ldmx4(bb + nt * 4, st + 16384u + sw128((uint32_t)(nrow * 128 + kb * 2)));
            }
            #pragma unroll
            for (int mt = 0; mt < 4; mt++)
                #pragma unroll
                for (int nj = 0; nj < 8; nj++)
                    mma16816(acc[mt][nj], ah + mt * 4, bb + nj * 2);
        }
    }

    #pragma unroll
    for (int mt = 0; mt < 4; mt++) {
        int r0 = m0 + wm + mt * 16 + (lane >> 2);
        #pragma unroll
        for (int nj = 0; nj < 8; nj++) {
            int col = n0 + wn + nj * 8 + (lane & 3) * 2;
            float b0 = __ldg(bias + col), b1 = __ldg(bias + col + 1);
            float* p = out + (size_t)r0 * DOUT + col;
            p[0] = acc[mt][nj][0] + b0;
            p[1] = acc[mt][nj][1] + b1;
            float* q = p + (size_t)8 * DOUT;
            q[0] = acc[mt][nj][2] + b0;
            q[1] = acc[mt][nj][3] + b1;
        }
    }
}

// ---------------------------------------------------------------------------
// kernel_launch
// ---------------------------------------------------------------------------
extern "C" void kernel_launch(void* const* d_in, const int* in_sizes, int n_in,
                              void* d_out, int out_size) {
    const float* x      = (const float*)d_in[0];
    const float* base_w = (const float*)d_in[1];
    const float* base_b = (const float*)d_in[2];
    const float* A      = (const float*)d_in[3];
    const float* Bm     = (const float*)d_in[4];
    const float* router = (const float*)d_in[5];
    float* out = (float*)d_out;

    cudaFuncSetAttribute(gemm_kernel, cudaFuncAttributeMaxDynamicSharedMemorySize, GEMM_SMEM);
    cudaFuncSetAttribute(hl_gemm_kernel, cudaFuncAttributeMaxDynamicSharedMemorySize, HL_SMEM);

    wprep_kernel<<<dim3(KCAT / 256, DOUT), 256>>>(base_w, Bm);
    w2prep_kernel<<<dim3(DIN / 256, 128), 256>>>(A, router);
    xconv_kernel<<<dim3(DIN / 256, T_TOK), 256>>>(x);
    hl_gemm_kernel<<<dim3(1, T_TOK / 64), 256, HL_SMEM>>>();
    hlpost_kernel<<<T_TOK, 128>>>();
    gemm_kernel<<<dim3(DOUT / BN, T_TOK / BM), 256, GEMM_SMEM>>>(base_b, out);
}